// round 1
// baseline (speedup 1.0000x reference)
#include <cuda_runtime.h>

#define NB    32
#define HWD   3136
#define CD    256
#define DIM   802816          // 56*56*256
#define KSEL  160564u         // ceil(0.2 * 802816)

// ---------------- static device scratch (no allocations allowed) ----------------
__device__ unsigned int g_hist[NB][4096];     // 512 KB
__device__ unsigned int g_cnt[NB];
__device__ unsigned int g_prefix[NB];         // selected top-12-bit bin
__device__ unsigned int g_krem[NB];           // residual rank within bin
__device__ unsigned int g_thresh[NB];         // exact kth-largest as ordered uint
__device__ unsigned int g_scratch[NB][DIM];   // ~103 MB worst-case candidate buffer

// order-preserving float -> uint map (ascending uint == ascending float)
__device__ __forceinline__ unsigned int f2u(float f) {
    unsigned int b = __float_as_uint(f);
    unsigned int mask = ((int)b >> 31) | 0x80000000u;  // neg: 0xFFFFFFFF, pos: 0x80000000
    return b ^ mask;
}

// ---------------- kernel 1: zero counters ----------------
__global__ void k_zero() {
    int i = blockIdx.x * blockDim.x + threadIdx.x;
    if (i < NB * 4096) ((unsigned int*)g_hist)[i] = 0u;
    if (i < NB) g_cnt[i] = 0u;
}

// ---------------- kernel 2: per-sample 4096-bin histogram of top 12 bits ----------------
__global__ void k_hist(const float* __restrict__ x) {
    __shared__ unsigned int sh[4096];
    for (int i = threadIdx.x; i < 4096; i += blockDim.x) sh[i] = 0u;
    __syncthreads();

    int b = blockIdx.y;
    const float4* xp = (const float4*)(x + (size_t)b * DIM);
    const int nvec = DIM / 4;
    for (int i = blockIdx.x * blockDim.x + threadIdx.x; i < nvec;
         i += gridDim.x * blockDim.x) {
        float4 v = xp[i];
        atomicAdd(&sh[f2u(v.x) >> 20], 1u);
        atomicAdd(&sh[f2u(v.y) >> 20], 1u);
        atomicAdd(&sh[f2u(v.z) >> 20], 1u);
        atomicAdd(&sh[f2u(v.w) >> 20], 1u);
    }
    __syncthreads();
    for (int i = threadIdx.x; i < 4096; i += blockDim.x) {
        unsigned int c = sh[i];
        if (c) atomicAdd(&g_hist[b][i], c);
    }
}

// ---------------- kernel 3: find top-12-bit bin containing the kth largest ----------------
__global__ void k_select1() {
    int b = blockIdx.x;
    int t = threadIdx.x;                 // 256 threads, 16 bins each (descending order)
    __shared__ unsigned int part[256];

    unsigned int loc[16];
    unsigned int s = 0;
    #pragma unroll
    for (int j = 0; j < 16; j++) {
        loc[j] = g_hist[b][4095 - (t * 16 + j)];
        s += loc[j];
    }
    part[t] = s;
    __syncthreads();
    // inclusive Hillis-Steele scan over 256 partials
    for (int off = 1; off < 256; off <<= 1) {
        unsigned int add = (t >= off) ? part[t - off] : 0u;
        __syncthreads();
        part[t] += add;
        __syncthreads();
    }
    unsigned int incl = part[t];
    unsigned int excl = incl - s;
    if (excl < KSEL && incl >= KSEL) {
        unsigned int cum = excl;
        #pragma unroll
        for (int j = 0; j < 16; j++) {
            unsigned int nc = cum + loc[j];
            if (cum < KSEL && nc >= KSEL) {
                g_prefix[b] = 4095 - (t * 16 + j);
                g_krem[b]   = KSEL - cum;
            }
            cum = nc;
        }
    }
}

// ---------------- kernel 4: compact candidates matching the 12-bit prefix ----------------
__global__ void k_compact(const float* __restrict__ x) {
    int b = blockIdx.y;
    unsigned int pre = g_prefix[b];
    const float4* xp = (const float4*)(x + (size_t)b * DIM);
    const int nvec = DIM / 4;
    int lane = threadIdx.x & 31;
    for (int i = blockIdx.x * blockDim.x + threadIdx.x; i < nvec;
         i += gridDim.x * blockDim.x) {
        float4 v = xp[i];
        unsigned int u[4] = {f2u(v.x), f2u(v.y), f2u(v.z), f2u(v.w)};
        #pragma unroll
        for (int j = 0; j < 4; j++) {
            bool m = (u[j] >> 20) == pre;
            unsigned int ball = __ballot_sync(0xffffffffu, m);
            if (ball) {
                int lead = __ffs(ball) - 1;
                unsigned int base = 0;
                if (lane == lead) base = atomicAdd(&g_cnt[b], (unsigned int)__popc(ball));
                base = __shfl_sync(0xffffffffu, base, lead);
                if (m) {
                    int off = __popc(ball & ((1u << lane) - 1u));
                    g_scratch[b][base + off] = u[j];
                }
            }
        }
    }
}

// ---------------- kernel 5: two 10-bit radix rounds on candidates -> exact threshold ----------------
__global__ void k_select2() {
    int b = blockIdx.x;
    int t = threadIdx.x;                 // 1024 threads
    __shared__ unsigned int h[1024];
    __shared__ unsigned int sc[1024];
    __shared__ unsigned int s_bin, s_krem;

    unsigned int n  = g_cnt[b];
    unsigned int kr = g_krem[b];
    const unsigned int* sp = g_scratch[b];

    // --- round 1: bits [19:10] ---
    h[t] = 0u; __syncthreads();
    for (unsigned int i = t; i < n; i += 1024)
        atomicAdd(&h[(sp[i] >> 10) & 1023u], 1u);
    __syncthreads();
    unsigned int mine = h[1023 - t];
    sc[t] = mine; __syncthreads();
    for (int off = 1; off < 1024; off <<= 1) {
        unsigned int add = (t >= off) ? sc[t - off] : 0u;
        __syncthreads();
        sc[t] += add; __syncthreads();
    }
    if (sc[t] >= kr && sc[t] - mine < kr) {
        s_bin = 1023 - t;
        s_krem = kr - (sc[t] - mine);
    }
    __syncthreads();
    unsigned int b1 = s_bin;
    kr = s_krem;
    __syncthreads();

    // --- round 2: bits [9:0] ---
    h[t] = 0u; __syncthreads();
    for (unsigned int i = t; i < n; i += 1024) {
        unsigned int u = sp[i];
        if (((u >> 10) & 1023u) == b1) atomicAdd(&h[u & 1023u], 1u);
    }
    __syncthreads();
    mine = h[1023 - t];
    sc[t] = mine; __syncthreads();
    for (int off = 1; off < 1024; off <<= 1) {
        unsigned int add = (t >= off) ? sc[t - off] : 0u;
        __syncthreads();
        sc[t] += add; __syncthreads();
    }
    if (sc[t] >= kr && sc[t] - mine < kr) {
        g_thresh[b] = (g_prefix[b] << 20) | (b1 << 10) | (unsigned int)(1023 - t);
    }
}

// ---------------- kernel 6: threshold + NHWC->NCHW-flatten transpose ----------------
__global__ void k_mask(const float* __restrict__ x, float* __restrict__ out) {
    __shared__ float tile[32][33];
    int b = blockIdx.z;
    unsigned int uth = g_thresh[b];
    const float* xb = x + (size_t)b * DIM;
    float* ob = out + (size_t)b * DIM;
    int hw0 = blockIdx.x * 32;
    int c0  = blockIdx.y * 32;
    int tx = threadIdx.x, ty = threadIdx.y;

    #pragma unroll
    for (int i = 0; i < 32; i += 8) {
        float v = xb[(size_t)(hw0 + ty + i) * CD + (c0 + tx)];
        tile[ty + i][tx] = (f2u(v) >= uth) ? v : 0.0f;
    }
    __syncthreads();
    #pragma unroll
    for (int i = 0; i < 32; i += 8) {
        ob[(size_t)(c0 + ty + i) * HWD + (hw0 + tx)] = tile[tx][ty + i];
    }
}

// ---------------- launch ----------------
extern "C" void kernel_launch(void* const* d_in, const int* in_sizes, int n_in,
                              void* d_out, int out_size) {
    const float* x = (const float*)d_in[0];
    float* out = (float*)d_out;

    k_zero<<<(NB * 4096 + 255) / 256, 256>>>();
    k_hist<<<dim3(98, NB), 256>>>(x);
    k_select1<<<NB, 256>>>();
    k_compact<<<dim3(98, NB), 256>>>(x);
    k_select2<<<NB, 1024>>>();
    k_mask<<<dim3(HWD / 32, CD / 32, NB), dim3(32, 8)>>>(x, out);
}

// round 3
// speedup vs baseline: 2.7540x; 2.7540x over previous
#include <cuda_runtime.h>

#define NB    32
#define HWD   3136
#define CD    256
#define DIM   802816          // 56*56*256
#define KSEL  160564u         // ceil(0.2 * 802816)
#define CBLK  98              // compact/hist blocks per sample
#define CHUNK (DIM / CBLK)    // 8192 elements per block (exact)

// ---------------- static device scratch (no allocations allowed) ----------------
__device__ unsigned int g_hist[NB][4096];     // 512 KB
__device__ unsigned int g_cnt[NB];
__device__ unsigned int g_prefix[NB];         // selected top-12-bit bin
__device__ unsigned int g_krem[NB];           // residual rank within bin
__device__ unsigned int g_thresh[NB];         // exact kth-largest as ordered uint
__device__ unsigned int g_scratch[NB][DIM];   // worst-case candidate buffer

// order-preserving float -> uint map (ascending uint == ascending float)
__device__ __forceinline__ unsigned int f2u(float f) {
    unsigned int b = __float_as_uint(f);
    unsigned int mask = ((int)b >> 31) | 0x80000000u;
    return b ^ mask;
}

// ---------------- kernel 1: zero counters ----------------
__global__ void k_zero() {
    int i = blockIdx.x * blockDim.x + threadIdx.x;
    if (i < NB * 4096) ((unsigned int*)g_hist)[i] = 0u;
    if (i < NB) g_cnt[i] = 0u;
}

// ---------------- kernel 2: per-sample 4096-bin histogram of top 12 bits ----------------
__global__ void k_hist(const float* __restrict__ x) {
    __shared__ unsigned int sh[4096];
    for (int i = threadIdx.x; i < 4096; i += blockDim.x) sh[i] = 0u;
    __syncthreads();

    int b = blockIdx.y;
    const float4* xp = (const float4*)(x + (size_t)b * DIM);
    const int nvec = DIM / 4;
    for (int i = blockIdx.x * blockDim.x + threadIdx.x; i < nvec;
         i += gridDim.x * blockDim.x) {
        float4 v = xp[i];
        atomicAdd(&sh[f2u(v.x) >> 20], 1u);
        atomicAdd(&sh[f2u(v.y) >> 20], 1u);
        atomicAdd(&sh[f2u(v.z) >> 20], 1u);
        atomicAdd(&sh[f2u(v.w) >> 20], 1u);
    }
    __syncthreads();
    for (int i = threadIdx.x; i < 4096; i += blockDim.x) {
        unsigned int c = sh[i];
        if (c) atomicAdd(&g_hist[b][i], c);
    }
}

// ---------------- kernel 3: find top-12-bit bin containing the kth largest ----------------
__global__ void k_select1() {
    int b = blockIdx.x;
    int t = threadIdx.x;                 // 256 threads, 16 bins each (descending)
    __shared__ unsigned int part[256];

    unsigned int loc[16];
    unsigned int s = 0;
    #pragma unroll
    for (int j = 0; j < 16; j++) {
        loc[j] = g_hist[b][4095 - (t * 16 + j)];
        s += loc[j];
    }
    part[t] = s;
    __syncthreads();
    for (int off = 1; off < 256; off <<= 1) {
        unsigned int add = (t >= off) ? part[t - off] : 0u;
        __syncthreads();
        part[t] += add;
        __syncthreads();
    }
    unsigned int incl = part[t];
    unsigned int excl = incl - s;
    if (excl < KSEL && incl >= KSEL) {
        unsigned int cum = excl;
        #pragma unroll
        for (int j = 0; j < 16; j++) {
            unsigned int nc = cum + loc[j];
            if (cum < KSEL && nc >= KSEL) {
                g_prefix[b] = 4095 - (t * 16 + j);
                g_krem[b]   = KSEL - cum;
            }
            cum = nc;
        }
    }
}

// ---------------- kernel 4: two-phase compact (ONE global atomic per block) ----------------
__global__ void k_compact(const float* __restrict__ x) {
    int b = blockIdx.y;
    unsigned int pre = g_prefix[b];
    // contiguous chunk per block so phase-2 re-read hits L2
    const float4* xp = (const float4*)(x + (size_t)b * DIM + (size_t)blockIdx.x * CHUNK);
    const int nvec = CHUNK / 4;          // 2048

    __shared__ unsigned int s_wcnt[8];
    __shared__ unsigned int s_base;
    __shared__ unsigned int s_off;
    int lane = threadIdx.x & 31;
    int wid  = threadIdx.x >> 5;

    // --- phase 1: count matches (pure streaming read) ---
    unsigned int cnt = 0;
    for (int i = threadIdx.x; i < nvec; i += blockDim.x) {
        float4 v = xp[i];
        cnt += ((f2u(v.x) >> 20) == pre);
        cnt += ((f2u(v.y) >> 20) == pre);
        cnt += ((f2u(v.z) >> 20) == pre);
        cnt += ((f2u(v.w) >> 20) == pre);
    }
    #pragma unroll
    for (int o = 16; o > 0; o >>= 1) cnt += __shfl_down_sync(0xffffffffu, cnt, o);
    if (lane == 0) s_wcnt[wid] = cnt;
    __syncthreads();
    if (threadIdx.x == 0) {
        unsigned int tot = 0;
        #pragma unroll
        for (int w = 0; w < 8; w++) tot += s_wcnt[w];
        s_base = tot ? atomicAdd(&g_cnt[b], tot) : 0u;
        s_off = 0u;
    }
    __syncthreads();
    unsigned int base = s_base;

    // --- phase 2: re-read (L2-hot) and write candidates via shared-atomic offsets ---
    unsigned int* dst = g_scratch[b];
    for (int i = threadIdx.x; i < nvec; i += blockDim.x) {
        float4 v = xp[i];
        unsigned int u[4] = {f2u(v.x), f2u(v.y), f2u(v.z), f2u(v.w)};
        #pragma unroll
        for (int j = 0; j < 4; j++) {
            bool m = (u[j] >> 20) == pre;
            unsigned int ball = __ballot_sync(0xffffffffu, m);
            if (ball) {
                int lead = __ffs(ball) - 1;
                unsigned int wbase = 0;
                if (lane == lead)
                    wbase = atomicAdd(&s_off, (unsigned int)__popc(ball));
                wbase = __shfl_sync(0xffffffffu, wbase, lead);
                if (m) {
                    int off = __popc(ball & ((1u << lane) - 1u));
                    dst[base + wbase + off] = u[j];
                }
            }
        }
    }
}

// ---------------- kernel 5: two 10-bit radix rounds on candidates -> exact threshold ----------------
__global__ void k_select2() {
    int b = blockIdx.x;
    int t = threadIdx.x;                 // 1024 threads
    __shared__ unsigned int h[1024];
    __shared__ unsigned int sc[1024];
    __shared__ unsigned int s_bin, s_krem;

    unsigned int n  = g_cnt[b];
    unsigned int kr = g_krem[b];
    const unsigned int* sp = g_scratch[b];

    // --- round 1: bits [19:10] ---
    h[t] = 0u; __syncthreads();
    for (unsigned int i = t; i < n; i += 1024)
        atomicAdd(&h[(sp[i] >> 10) & 1023u], 1u);
    __syncthreads();
    unsigned int mine = h[1023 - t];
    sc[t] = mine; __syncthreads();
    for (int off = 1; off < 1024; off <<= 1) {
        unsigned int add = (t >= off) ? sc[t - off] : 0u;
        __syncthreads();
        sc[t] += add; __syncthreads();
    }
    if (sc[t] >= kr && sc[t] - mine < kr) {
        s_bin = 1023 - t;
        s_krem = kr - (sc[t] - mine);
    }
    __syncthreads();
    unsigned int b1 = s_bin;
    kr = s_krem;
    __syncthreads();

    // --- round 2: bits [9:0] ---
    h[t] = 0u; __syncthreads();
    for (unsigned int i = t; i < n; i += 1024) {
        unsigned int u = sp[i];
        if (((u >> 10) & 1023u) == b1) atomicAdd(&h[u & 1023u], 1u);
    }
    __syncthreads();
    mine = h[1023 - t];
    sc[t] = mine; __syncthreads();
    for (int off = 1; off < 1024; off <<= 1) {
        unsigned int add = (t >= off) ? sc[t - off] : 0u;
        __syncthreads();
        sc[t] += add; __syncthreads();
    }
    if (sc[t] >= kr && sc[t] - mine < kr) {
        g_thresh[b] = (g_prefix[b] << 20) | (b1 << 10) | (unsigned int)(1023 - t);
    }
}

// ---------------- kernel 6: threshold + NHWC->NCHW-flatten transpose ----------------
__global__ void k_mask(const float* __restrict__ x, float* __restrict__ out) {
    __shared__ float tile[32][33];
    int b = blockIdx.z;
    unsigned int uth = g_thresh[b];
    const float* xb = x + (size_t)b * DIM;
    float* ob = out + (size_t)b * DIM;
    int hw0 = blockIdx.x * 32;
    int c0  = blockIdx.y * 32;
    int tx = threadIdx.x, ty = threadIdx.y;

    #pragma unroll
    for (int i = 0; i < 32; i += 8) {
        float v = xb[(size_t)(hw0 + ty + i) * CD + (c0 + tx)];
        tile[ty + i][tx] = (f2u(v) >= uth) ? v : 0.0f;
    }
    __syncthreads();
    #pragma unroll
    for (int i = 0; i < 32; i += 8) {
        ob[(size_t)(c0 + ty + i) * HWD + (hw0 + tx)] = tile[tx][ty + i];
    }
}

// ---------------- launch ----------------
extern "C" void kernel_launch(void* const* d_in, const int* in_sizes, int n_in,
                              void* d_out, int out_size) {
    const float* x = (const float*)d_in[0];
    float* out = (float*)d_out;

    k_zero<<<(NB * 4096 + 255) / 256, 256>>>();
    k_hist<<<dim3(CBLK, NB), 256>>>(x);
    k_select1<<<NB, 256>>>();
    k_compact<<<dim3(CBLK, NB), 256>>>(x);
    k_select2<<<NB, 1024>>>();
    k_mask<<<dim3(HWD / 32, CD / 32, NB), dim3(32, 8)>>>(x, out);
}